// round 8
// baseline (speedup 1.0000x reference)
#include <cuda_runtime.h>
#include <cuda_bf16.h>
#include <mma.h>
#include <math.h>
#include <cstdint>

using namespace nvcuda;
typedef __nv_bfloat16 bf16;

#define LN_EPS 1e-5f

// persistent scratch (device globals: allocation-free)
__device__ float g_xres[(size_t)200704 * 192];        // mid residual
__device__ bf16  g_qkv [(size_t)200704 * 576];        // LN1 @ Wqkv^T + b
__device__ bf16  g_attno[(size_t)200704 * 192];       // attention output (pre-proj)
__device__ bf16  g_hmid[(size_t)200704 * 768];        // GELU(fc1)
__device__ bf16  g_wqkv[576 * 192];
__device__ bf16  g_wproj[192 * 192];
__device__ bf16  g_wfc1[768 * 192];
__device__ bf16  g_wfc2[192 * 768];

typedef wmma::fragment<wmma::matrix_a, 16, 16, 16, bf16, wmma::row_major> FA;
typedef wmma::fragment<wmma::matrix_b, 16, 16, 16, bf16, wmma::col_major> FBc;
typedef wmma::fragment<wmma::matrix_b, 16, 16, 16, bf16, wmma::row_major> FBr;
typedef wmma::fragment<wmma::accumulator, 16, 16, 16, float> FC;

// ---------------------------------------------------------------------------
__global__ void cvt_all(const float* __restrict__ wqkv, const float* __restrict__ wproj,
                        const float* __restrict__ wfc1, const float* __restrict__ wfc2)
{
    int i = blockIdx.x * 256 + threadIdx.x;
    if (i < 110592) g_wqkv[i]  = __float2bfloat16(wqkv[i]);
    if (i < 36864)  g_wproj[i] = __float2bfloat16(wproj[i]);
    if (i < 147456) {
        g_wfc1[i] = __float2bfloat16(wfc1[i]);
        g_wfc2[i] = __float2bfloat16(wfc2[i]);
    }
}

// ---------------------------------------------------------------------------
// Register-buffered tile staging (256-thread CTA).
// B tile: 96x96 bf16 -> 1152 x 16B; threads 0..127 carry 5, 128..255 carry 4.
// A chunk: 128x96 bf16 -> 1536 x 16B; 6 per thread exactly.
// ---------------------------------------------------------------------------
__device__ __forceinline__ void ldg_B96(uint4 v[5], const bf16* __restrict__ W,
                                        int ldw, int n0, int k0, int tid)
{
    const bf16* src = W + (size_t)n0 * ldw + k0;
#pragma unroll
    for (int i = 0; i < 5; i++) {
        int idx = tid + i * 256;
        if (idx < 1152) {
            int r = idx / 12, ch = (idx - r * 12) * 8;
            v[i] = *(const uint4*)(src + (size_t)r * ldw + ch);
        }
    }
}
__device__ __forceinline__ void sts_B96(const uint4 v[5], bf16* Bs, int tid)
{
#pragma unroll
    for (int i = 0; i < 5; i++) {
        int idx = tid + i * 256;
        if (idx < 1152) {
            int r = idx / 12, ch = (idx - r * 12) * 8;
            *(uint4*)(Bs + r * 104 + ch) = v[i];
        }
    }
}
__device__ __forceinline__ void ldg_A96(uint4 v[6], const bf16* __restrict__ src,
                                        int lds, int tid)
{
#pragma unroll
    for (int i = 0; i < 6; i++) {
        int idx = tid + i * 256;            // < 1536 always
        int r = idx / 12, ch = (idx - r * 12) * 8;
        v[i] = *(const uint4*)(src + (size_t)r * lds + ch);
    }
}
__device__ __forceinline__ void sts_A96(const uint4 v[6], bf16* As, int tid)
{
#pragma unroll
    for (int i = 0; i < 6; i++) {
        int idx = tid + i * 256;
        int r = idx / 12, ch = (idx - r * 12) * 8;
        *(uint4*)(As + r * 104 + ch) = v[i];
    }
}

// ---------------------------------------------------------------------------
// smem layout (K=192 kernels): As 128x200 bf16 (51200) | Bbuf0/1 96x104 bf16
// (19968 each) | per-warp epi scratch 8x(16x20 f32) (10240)  = 101376 B
// ---------------------------------------------------------------------------
#define G192_SM (51200 + 2 * 19968 + 10240)
#define FC2_SM  (2 * 26624 + 2 * 19968 + 10240)

__device__ __forceinline__ void stage_A_ln(bf16* As, const float* __restrict__ xr,
                                           const float* __restrict__ g,
                                           const float* __restrict__ b,
                                           int wid, int lane)
{
    for (int r = wid; r < 128; r += 8) {
        float v[6]; float s = 0.f;
#pragma unroll
        for (int j = 0; j < 6; j++) { v[j] = xr[r * 192 + j * 32 + lane]; s += v[j]; }
#pragma unroll
        for (int o = 16; o; o >>= 1) s += __shfl_xor_sync(0xffffffffu, s, o);
        float mu = s * (1.f / 192.f);
        float va = 0.f;
#pragma unroll
        for (int j = 0; j < 6; j++) { float d = v[j] - mu; va += d * d; }
#pragma unroll
        for (int o = 16; o; o >>= 1) va += __shfl_xor_sync(0xffffffffu, va, o);
        float rstd = rsqrtf(va * (1.f / 192.f) + LN_EPS);
#pragma unroll
        for (int j = 0; j < 6; j++) {
            int c = j * 32 + lane;
            As[r * 200 + c] = __float2bfloat16((v[j] - mu) * rstd * g[c] + b[c]);
        }
    }
}

// mma over one 96-K chunk: A from As (ld ldA, k offset kbase), B from Bs (ld 104)
__device__ __forceinline__ void mma_chunk(const bf16* As, int ldA, int kbase,
                                          const bf16* Bs, int mt, int ng, FC acc[6])
{
#pragma unroll
    for (int kk = 0; kk < 96; kk += 16) {
        FA a0, a1;
        wmma::load_matrix_sync(a0, As + (mt * 32) * ldA + kbase + kk, ldA);
        wmma::load_matrix_sync(a1, As + (mt * 32 + 16) * ldA + kbase + kk, ldA);
#pragma unroll
        for (int j = 0; j < 3; j++) {
            FBc b;
            wmma::load_matrix_sync(b, Bs + (ng * 48 + j * 16) * 104 + kk, 104);
            wmma::mma_sync(acc[j],     a0, b, acc[j]);
            wmma::mma_sync(acc[j + 3], a1, b, acc[j + 3]);
        }
    }
}

// per-warp barrier-free epilogue. OP: 0=qkv(+b->bf16) 1=proj(+b+x->f32)
// 2=fc1(+b,gelu->bf16) 3=fc2(+b+xres->out f32)
template <int OP>
__device__ __forceinline__ void epi_frags(float* ws, FC acc[6], int mt, int ng,
                                          int cbase, int row0,
                                          const float* __restrict__ xin,
                                          const float* __restrict__ bias,
                                          float* __restrict__ outp, int lane)
{
#pragma unroll
    for (int j = 0; j < 6; j++) {
        int r0 = row0 + mt * 32 + (j >= 3 ? 16 : 0);
        int c0 = cbase + ng * 48 + (j % 3) * 16;
        wmma::store_matrix_sync(ws, acc[j], 20, wmma::mem_row_major);
        __syncwarp();
        int rr = lane >> 1, cc = (lane & 1) * 8;
        const float* sp = ws + rr * 20 + cc;
        int gr = r0 + rr, gc = c0 + cc;
        if (OP == 0) {
            uint4 u; bf16* pb = (bf16*)&u;
#pragma unroll
            for (int q = 0; q < 8; q++) pb[q] = __float2bfloat16(sp[q] + bias[gc + q]);
            *(uint4*)(g_qkv + (size_t)gr * 576 + gc) = u;
        } else if (OP == 1) {
#pragma unroll
            for (int q = 0; q < 8; q++) {
                size_t gi = (size_t)gr * 192 + gc + q;
                g_xres[gi] = sp[q] + bias[gc + q] + xin[gi];
            }
        } else if (OP == 2) {
            uint4 u; bf16* pb = (bf16*)&u;
#pragma unroll
            for (int q = 0; q < 8; q++) {
                float v = sp[q] + bias[gc + q];
                v = 0.5f * v * (1.f + erff(v * 0.70710678118654752f));
                pb[q] = __float2bfloat16(v);
            }
            *(uint4*)(g_hmid + (size_t)gr * 768 + gc) = u;
        } else {
#pragma unroll
            for (int q = 0; q < 8; q++) {
                size_t gi = (size_t)gr * 192 + gc + q;
                outp[gi] = sp[q] + bias[gc + q] + g_xres[gi];
            }
        }
        __syncwarp();
    }
}

// ---------------------------------------------------------------------------
// Unified K=192 GEMM: CTA = 128 rows, N = NSLICES*96, reg-pipelined 96x96 B
// tiles. OP: 0 = qkv (LN from xin), 1 = proj (A = g_attno, residual xin),
// 2 = fc1 (LN from g_xres).
// W is resolved INSIDE device code (never pass __device__ symbols from host!)
// ---------------------------------------------------------------------------
template <int NSLICES, int OP>
__global__ __launch_bounds__(256, 2) void gemm192_kernel(
    const float* __restrict__ xin, const float* __restrict__ lng,
    const float* __restrict__ lnb, const float* __restrict__ bias)
{
    extern __shared__ char smc[];
    bf16*  As   = (bf16*)smc;
    bf16*  Bb0  = (bf16*)(smc + 51200);
    bf16*  Bb1  = (bf16*)(smc + 51200 + 19968);
    float* epi  = (float*)(smc + 51200 + 2 * 19968);

    const bf16* W = (OP == 0) ? g_wqkv : ((OP == 1) ? g_wproj : g_wfc1);

    const int tid = threadIdx.x, wid = tid >> 5, lane = tid & 31;
    const int row0 = blockIdx.x * 128;
    const int mt = wid & 3, ng = wid >> 2;
    float* ws = epi + wid * 320;

    uint4 breg[5];
    ldg_B96(breg, W, 192, 0, 0, tid);      // tile 0 in flight

    if (OP == 0) stage_A_ln(As, xin + (size_t)row0 * 192, lng, lnb, wid, lane);
    else if (OP == 2) stage_A_ln(As, g_xres + (size_t)row0 * 192, lng, lnb, wid, lane);
    else {
        const bf16* src = g_attno + (size_t)row0 * 192;
        for (int idx = tid; idx < 128 * 24; idx += 256) {
            int r = idx / 24, ch = (idx - r * 24) * 8;
            *(uint4*)(As + r * 200 + ch) = *(const uint4*)(src + (size_t)r * 192 + ch);
        }
    }
    sts_B96(breg, Bb0, tid);

    FC acc[6];
#pragma unroll
    for (int j = 0; j < 6; j++) wmma::fill_fragment(acc[j], 0.f);

    const int T = NSLICES * 2;
    for (int t = 0; t < T; t++) {
        const int s = t >> 1, c = t & 1;
        bf16* Bcur = (t & 1) ? Bb1 : Bb0;
        bf16* Bnxt = (t & 1) ? Bb0 : Bb1;
        __syncthreads();                     // Bcur ready; all done reading Bnxt
        if (t + 1 < T)
            ldg_B96(breg, W, 192, ((t + 1) >> 1) * 96, ((t + 1) & 1) * 96, tid);
        mma_chunk(As, 200, c * 96, Bcur, mt, ng, acc);
        if (t + 1 < T)
            sts_B96(breg, Bnxt, tid);
        if (c == 1) {
            epi_frags<OP>(ws, acc, mt, ng, s * 96, row0, xin, bias, (float*)0, lane);
#pragma unroll
            for (int j = 0; j < 6; j++) wmma::fill_fragment(acc[j], 0.f);
        }
    }
}

// ---------------------------------------------------------------------------
// FC2: grid (1568, 2); CTA = 128 rows x 96 cols, K = 768 in 8 reg-pipelined
// chunks, persistent acc; + residual -> out
// ---------------------------------------------------------------------------
__global__ __launch_bounds__(256, 2) void fc2_kernel(
    const float* __restrict__ bfc2, float* __restrict__ out)
{
    extern __shared__ char smc[];
    bf16*  Ab0  = (bf16*)smc;
    bf16*  Ab1  = (bf16*)(smc + 26624);
    bf16*  Bb0  = (bf16*)(smc + 2 * 26624);
    bf16*  Bb1  = (bf16*)(smc + 2 * 26624 + 19968);
    float* epi  = (float*)(smc + 2 * 26624 + 2 * 19968);

    const int tid = threadIdx.x, wid = tid >> 5, lane = tid & 31;
    const int row0 = blockIdx.x * 128;
    const int n0 = blockIdx.y * 96;
    const int mt = wid & 3, ng = wid >> 2;
    float* ws = epi + wid * 320;

    uint4 areg[6], breg[5];
    ldg_A96(areg, g_hmid + (size_t)row0 * 768, 768, tid);
    ldg_B96(breg, g_wfc2, 768, n0, 0, tid);
    sts_A96(areg, Ab0, tid);
    sts_B96(breg, Bb0, tid);

    FC acc[6];
#pragma unroll
    for (int j = 0; j < 6; j++) wmma::fill_fragment(acc[j], 0.f);

    for (int t = 0; t < 8; t++) {
        bf16* Acur = (t & 1) ? Ab1 : Ab0;
        bf16* Bcur = (t & 1) ? Bb1 : Bb0;
        bf16* Anxt = (t & 1) ? Ab0 : Ab1;
        bf16* Bnxt = (t & 1) ? Bb0 : Bb1;
        __syncthreads();
        if (t + 1 < 8) {
            ldg_A96(areg, g_hmid + (size_t)row0 * 768 + (t + 1) * 96, 768, tid);
            ldg_B96(breg, g_wfc2, 768, n0, (t + 1) * 96, tid);
        }
        mma_chunk(Acur, 104, 0, Bcur, mt, ng, acc);
        if (t + 1 < 8) {
            sts_A96(areg, Anxt, tid);
            sts_B96(breg, Bnxt, tid);
        }
    }
    epi_frags<3>(ws, acc, mt, ng, n0, row0, (const float*)0, bfc2, out, lane);
}

// ---------------------------------------------------------------------------
// attention core per (window, head): S -> masked softmax -> PV
// ---------------------------------------------------------------------------
#define AT_SM 41984

__global__ __launch_bounds__(256) void attn_core(const int* __restrict__ mask)
{
    extern __shared__ char smc[];
    bf16*  qs    = (bf16*)smc;               // 64x40
    bf16*  ks    = (bf16*)(smc + 5120);
    bf16*  vs    = (bf16*)(smc + 10240);
    float* S     = (float*)(smc + 15360);    // 64x68 f32
    bf16*  P     = (bf16*)(smc + 32768);     // 64x72
    float* pvbuf = (float*)(smc + 15360);    // alias S

    const int tid = threadIdx.x, wid = tid >> 5, lane = tid & 31;
    const int win = blockIdx.x, h = blockIdx.y;
    const size_t base = (size_t)(win * 49) * 576;

    {
        const int r = tid >> 2, c8 = (tid & 3) * 8;
        uint4 z; z.x = z.y = z.z = z.w = 0u;
#pragma unroll
        for (int m = 0; m < 3; m++) {
            bf16* dst = (m == 0) ? qs : ((m == 1) ? ks : vs);
            uint4 val = z;
            if (r < 49)
                val = *(const uint4*)(g_qkv + base + (size_t)r * 576 + m * 192 + h * 32 + c8);
            *(uint4*)(dst + r * 40 + c8) = val;
        }
    }
    __syncthreads();

#pragma unroll
    for (int it = 0; it < 2; it++) {
        int t = wid + it * 8;
        int mt = t & 3, nt = t >> 2;
        FC c;
        wmma::fill_fragment(c, 0.f);
#pragma unroll
        for (int k0 = 0; k0 < 32; k0 += 16) {
            FA a;
            wmma::load_matrix_sync(a, qs + mt * 16 * 40 + k0, 40);
            FBc b;
            wmma::load_matrix_sync(b, ks + nt * 16 * 40 + k0, 40);
            wmma::mma_sync(c, a, b, c);
        }
        wmma::store_matrix_sync(S + mt * 16 * 68 + nt * 16, c, 68, wmma::mem_row_major);
    }
    __syncthreads();

    {
        const float scale = 0.17677669529663687f;
        const int* mrow_base = mask + (size_t)win * 49 * 49;
        for (int r = wid; r < 49; r += 8) {
            const int* mrow = mrow_base + r * 49;
            int j2 = lane + 32;
            float s1 = (mrow[lane] == 0) ? -1e30f : S[r * 68 + lane] * scale;
            float s2 = (j2 < 49 && mrow[j2] != 0) ? S[r * 68 + j2] * scale : -1e30f;
            float m = fmaxf(s1, s2);
#pragma unroll
            for (int o = 16; o; o >>= 1) m = fmaxf(m, __shfl_xor_sync(0xffffffffu, m, o));
            float e1 = __expf(s1 - m);
            float e2 = (j2 < 49) ? __expf(s2 - m) : 0.f;
            float sum = e1 + e2;
#pragma unroll
            for (int o = 16; o; o >>= 1) sum += __shfl_xor_sync(0xffffffffu, sum, o);
            float inv = 1.f / sum;
            P[r * 72 + lane] = __float2bfloat16(e1 * inv);
            P[r * 72 + j2]   = __float2bfloat16(e2 * inv);
        }
    }
    __syncthreads();

    {
        int mt = wid & 3, nt = wid >> 2;
        FC c;
        wmma::fill_fragment(c, 0.f);
#pragma unroll
        for (int k0 = 0; k0 < 64; k0 += 16) {
            FA a;
            wmma::load_matrix_sync(a, P + mt * 16 * 72 + k0, 72);
            FBr b;
            wmma::load_matrix_sync(b, vs + k0 * 40 + nt * 16, 40);
            wmma::mma_sync(c, a, b, c);
        }
        wmma::store_matrix_sync(pvbuf + mt * 16 * 40 + nt * 16, c, 40, wmma::mem_row_major);
    }
    __syncthreads();

    for (int idx = tid; idx < 49 * 32; idx += 256) {
        int r = idx >> 5, c = idx & 31;
        g_attno[(size_t)(win * 49 + r) * 192 + h * 32 + c] = __float2bfloat16(pvbuf[r * 40 + c]);
    }
}

// ---------------------------------------------------------------------------

extern "C" void kernel_launch(void* const* d_in, const int* in_sizes, int n_in,
                              void* d_out, int out_size)
{
    const float* x     = (const float*)d_in[0];
    const int*   msk   = (const int*)  d_in[1];
    const float* ln1g  = (const float*)d_in[2];
    const float* ln1b  = (const float*)d_in[3];
    const float* bqkv  = (const float*)d_in[5];
    const float* bproj = (const float*)d_in[7];
    const float* ln2g  = (const float*)d_in[8];
    const float* ln2b  = (const float*)d_in[9];
    const float* bfc1  = (const float*)d_in[11];
    const float* bfc2  = (const float*)d_in[13];
    float* out = (float*)d_out;

    cudaFuncSetAttribute(gemm192_kernel<6, 0>, cudaFuncAttributeMaxDynamicSharedMemorySize, G192_SM);
    cudaFuncSetAttribute(gemm192_kernel<2, 1>, cudaFuncAttributeMaxDynamicSharedMemorySize, G192_SM);
    cudaFuncSetAttribute(gemm192_kernel<8, 2>, cudaFuncAttributeMaxDynamicSharedMemorySize, G192_SM);
    cudaFuncSetAttribute(fc2_kernel, cudaFuncAttributeMaxDynamicSharedMemorySize, FC2_SM);
    cudaFuncSetAttribute(attn_core,  cudaFuncAttributeMaxDynamicSharedMemorySize, AT_SM);

    cvt_all<<<576, 256>>>((const float*)d_in[4], (const float*)d_in[6],
                          (const float*)d_in[10], (const float*)d_in[12]);
    gemm192_kernel<6, 0><<<1568, 256, G192_SM>>>(x, ln1g, ln1b, bqkv);
    attn_core<<<dim3(4096, 6), 256, AT_SM>>>(msk);
    gemm192_kernel<2, 1><<<1568, 256, G192_SM>>>(x, (const float*)0, (const float*)0, bproj);
    gemm192_kernel<8, 2><<<1568, 256, G192_SM>>>((const float*)0, ln2g, ln2b, bfc1);
    fc2_kernel<<<dim3(1568, 2), 256, FC2_SM>>>(bfc2, out);
}

// round 9
// speedup vs baseline: 1.1098x; 1.1098x over previous
#include <cuda_runtime.h>
#include <cuda_bf16.h>
#include <mma.h>
#include <math.h>
#include <cstdint>

using namespace nvcuda;
typedef __nv_bfloat16 bf16;

#define LN_EPS 1e-5f

// persistent scratch (device globals: allocation-free)
__device__ float g_xres[(size_t)200704 * 192];        // mid residual
__device__ bf16  g_qkv [(size_t)200704 * 576];        // LN1 @ Wqkv^T + b
__device__ bf16  g_attno[(size_t)200704 * 192];       // attention output (pre-proj)
__device__ bf16  g_hmid[(size_t)200704 * 768];        // GELU(fc1)
__device__ bf16  g_wqkv[576 * 192];
__device__ bf16  g_wproj[192 * 192];
__device__ bf16  g_wfc1[768 * 192];
__device__ bf16  g_wfc2[192 * 768];

typedef wmma::fragment<wmma::matrix_a, 16, 16, 16, bf16, wmma::row_major> FA;
typedef wmma::fragment<wmma::matrix_b, 16, 16, 16, bf16, wmma::col_major> FBc;
typedef wmma::fragment<wmma::matrix_b, 16, 16, 16, bf16, wmma::row_major> FBr;
typedef wmma::fragment<wmma::accumulator, 16, 16, 16, float> FC;

// ---------------------------------------------------------------------------
__device__ __forceinline__ void cpa16(void* smem_dst, const void* gsrc) {
    unsigned int a = (unsigned int)__cvta_generic_to_shared(smem_dst);
    asm volatile("cp.async.cg.shared.global [%0], [%1], 16;\n" :: "r"(a), "l"(gsrc));
}
#define CP_COMMIT() asm volatile("cp.async.commit_group;\n" ::: "memory")
#define CP_WAIT0()  asm volatile("cp.async.wait_group 0;\n" ::: "memory")

// ---------------------------------------------------------------------------
__global__ void cvt_all(const float* __restrict__ wqkv, const float* __restrict__ wproj,
                        const float* __restrict__ wfc1, const float* __restrict__ wfc2)
{
    int i = blockIdx.x * 256 + threadIdx.x;
    if (i < 110592) g_wqkv[i]  = __float2bfloat16(wqkv[i]);
    if (i < 36864)  g_wproj[i] = __float2bfloat16(wproj[i]);
    if (i < 147456) {
        g_wfc1[i] = __float2bfloat16(wfc1[i]);
        g_wfc2[i] = __float2bfloat16(wfc2[i]);
    }
}

// ---------------------------------------------------------------------------
// smem layout (K=192 kernels): As 128x200 bf16 (51200) | Bbuf0/1 96x104 bf16
// (19968 each) | per-warp epi scratch 8x(16x20 f32) (10240)  = 101376 B
// ---------------------------------------------------------------------------
#define G192_SM (51200 + 2 * 19968 + 10240)
#define FC2_SM  (2 * 26624 + 2 * 19968 + 10240)

__device__ __forceinline__ void stage_A_ln(bf16* As, const float* __restrict__ xr,
                                           const float* __restrict__ g,
                                           const float* __restrict__ b,
                                           int wid, int lane)
{
    for (int r = wid; r < 128; r += 8) {
        float v[6]; float s = 0.f;
#pragma unroll
        for (int j = 0; j < 6; j++) { v[j] = xr[r * 192 + j * 32 + lane]; s += v[j]; }
#pragma unroll
        for (int o = 16; o; o >>= 1) s += __shfl_xor_sync(0xffffffffu, s, o);
        float mu = s * (1.f / 192.f);
        float va = 0.f;
#pragma unroll
        for (int j = 0; j < 6; j++) { float d = v[j] - mu; va += d * d; }
#pragma unroll
        for (int o = 16; o; o >>= 1) va += __shfl_xor_sync(0xffffffffu, va, o);
        float rstd = rsqrtf(va * (1.f / 192.f) + LN_EPS);
#pragma unroll
        for (int j = 0; j < 6; j++) {
            int c = j * 32 + lane;
            As[r * 200 + c] = __float2bfloat16((v[j] - mu) * rstd * g[c] + b[c]);
        }
    }
}

// async-copy one 96x96 B tile (rows of W[N,K] at n0.., cols k0..): 1152 x 16B
__device__ __forceinline__ void copy_B_tile(bf16* Bs, const bf16* __restrict__ W,
                                            int ldw, int n0, int k0, int tid)
{
    const bf16* src = W + (size_t)n0 * ldw + k0;
    for (int idx = tid; idx < 96 * 12; idx += 256) {
        int r = idx / 12, ch = (idx - r * 12) * 8;
        cpa16(Bs + r * 104 + ch, src + (size_t)r * ldw + ch);
    }
}

// async-copy 128x96 A chunk (ld 104)
__device__ __forceinline__ void copy_A_chunk(bf16* Ad, const bf16* __restrict__ src,
                                             int lds, int tid)
{
    for (int idx = tid; idx < 128 * 12; idx += 256) {
        int r = idx / 12, ch = (idx - r * 12) * 8;
        cpa16(Ad + r * 104 + ch, src + (size_t)r * lds + ch);
    }
}

// mma over one 96-K chunk: A from As (ld ldA, k offset kbase), B from Bs (ld 104)
__device__ __forceinline__ void mma_chunk(const bf16* As, int ldA, int kbase,
                                          const bf16* Bs, int mt, int ng, FC acc[6])
{
#pragma unroll
    for (int kk = 0; kk < 96; kk += 16) {
        FA a0, a1;
        wmma::load_matrix_sync(a0, As + (mt * 32) * ldA + kbase + kk, ldA);
        wmma::load_matrix_sync(a1, As + (mt * 32 + 16) * ldA + kbase + kk, ldA);
#pragma unroll
        for (int j = 0; j < 3; j++) {
            FBc b;
            wmma::load_matrix_sync(b, Bs + (ng * 48 + j * 16) * 104 + kk, 104);
            wmma::mma_sync(acc[j],     a0, b, acc[j]);
            wmma::mma_sync(acc[j + 3], a1, b, acc[j + 3]);
        }
    }
}

// per-warp barrier-free epilogue. OP: 0=qkv(+b->bf16) 1=proj(+b+x->f32)
// 2=fc1(+b,gelu->bf16) 3=fc2(+b+xres->out f32)
template <int OP>
__device__ __forceinline__ void epi_frags(float* ws, FC acc[6], int mt, int ng,
                                          int cbase, int row0,
                                          const float* __restrict__ xin,
                                          const float* __restrict__ bias,
                                          float* __restrict__ outp, int lane)
{
#pragma unroll
    for (int j = 0; j < 6; j++) {
        int r0 = row0 + mt * 32 + (j >= 3 ? 16 : 0);
        int c0 = cbase + ng * 48 + (j % 3) * 16;
        wmma::store_matrix_sync(ws, acc[j], 20, wmma::mem_row_major);
        __syncwarp();
        int rr = lane >> 1, cc = (lane & 1) * 8;
        const float* sp = ws + rr * 20 + cc;
        int gr = r0 + rr, gc = c0 + cc;
        if (OP == 0) {
            uint4 u; bf16* pb = (bf16*)&u;
#pragma unroll
            for (int q = 0; q < 8; q++) pb[q] = __float2bfloat16(sp[q] + bias[gc + q]);
            *(uint4*)(g_qkv + (size_t)gr * 576 + gc) = u;
        } else if (OP == 1) {
#pragma unroll
            for (int q = 0; q < 8; q++) {
                size_t gi = (size_t)gr * 192 + gc + q;
                g_xres[gi] = sp[q] + bias[gc + q] + xin[gi];
            }
        } else if (OP == 2) {
            uint4 u; bf16* pb = (bf16*)&u;
#pragma unroll
            for (int q = 0; q < 8; q++) {
                float v = sp[q] + bias[gc + q];
                v = 0.5f * v * (1.f + erff(v * 0.70710678118654752f));
                pb[q] = __float2bfloat16(v);
            }
            *(uint4*)(g_hmid + (size_t)gr * 768 + gc) = u;
        } else {
#pragma unroll
            for (int q = 0; q < 8; q++) {
                size_t gi = (size_t)gr * 192 + gc + q;
                outp[gi] = sp[q] + bias[gc + q] + g_xres[gi];
            }
        }
        __syncwarp();
    }
}

// ---------------------------------------------------------------------------
// Unified K=192 GEMM: CTA = 128 rows, N = NSLICES*96, cp.async-pipelined
// 96x96 B tiles. OP: 0 = qkv (LN from xin), 1 = proj (A = g_attno, residual
// xin), 2 = fc1 (LN from g_xres).
// W is resolved INSIDE device code (never pass __device__ symbols from host!)
// ---------------------------------------------------------------------------
template <int NSLICES, int OP>
__global__ __launch_bounds__(256, 2) void gemm192_kernel(
    const float* __restrict__ xin, const float* __restrict__ lng,
    const float* __restrict__ lnb, const float* __restrict__ bias)
{
    extern __shared__ char smc[];
    bf16*  As   = (bf16*)smc;
    bf16*  Bb0  = (bf16*)(smc + 51200);
    bf16*  Bb1  = (bf16*)(smc + 51200 + 19968);
    float* epi  = (float*)(smc + 51200 + 2 * 19968);

    const bf16* W = (OP == 0) ? g_wqkv : ((OP == 1) ? g_wproj : g_wfc1);

    const int tid = threadIdx.x, wid = tid >> 5, lane = tid & 31;
    const int row0 = blockIdx.x * 128;
    const int mt = wid & 3, ng = wid >> 2;
    float* ws = epi + wid * 320;

    // prefetch tile 0 (and A for OP1) in one async group
    copy_B_tile(Bb0, W, 192, 0, 0, tid);
    if (OP == 1) {
        const bf16* src = g_attno + (size_t)row0 * 192;
        for (int idx = tid; idx < 128 * 24; idx += 256) {
            int r = idx / 24, ch = (idx - r * 24) * 8;
            cpa16(As + r * 200 + ch, src + (size_t)r * 192 + ch);
        }
    }
    CP_COMMIT();

    if (OP == 0) stage_A_ln(As, xin + (size_t)row0 * 192, lng, lnb, wid, lane);
    if (OP == 2) stage_A_ln(As, g_xres + (size_t)row0 * 192, lng, lnb, wid, lane);

    FC acc[6];
#pragma unroll
    for (int j = 0; j < 6; j++) wmma::fill_fragment(acc[j], 0.f);

    const int T = NSLICES * 2;
    for (int t = 0; t < T; t++) {
        const int s = t >> 1, c = t & 1;
        bf16* Bcur = (t & 1) ? Bb1 : Bb0;
        bf16* Bnxt = (t & 1) ? Bb0 : Bb1;
        CP_WAIT0();
        __syncthreads();            // Bcur ready; everyone done reading Bnxt
        if (t + 1 < T) {
            copy_B_tile(Bnxt, W, 192, ((t + 1) >> 1) * 96, ((t + 1) & 1) * 96, tid);
            CP_COMMIT();
        }
        mma_chunk(As, 200, c * 96, Bcur, mt, ng, acc);
        if (c == 1) {
            epi_frags<OP>(ws, acc, mt, ng, s * 96, row0, xin, bias, (float*)0, lane);
#pragma unroll
            for (int j = 0; j < 6; j++) wmma::fill_fragment(acc[j], 0.f);
        }
    }
}

// ---------------------------------------------------------------------------
// FC2: grid (1568, 2); CTA = 128 rows x 96 cols, K = 768 in 8 cp.async-
// pipelined chunks, persistent acc; + residual -> out
// ---------------------------------------------------------------------------
__global__ __launch_bounds__(256, 2) void fc2_kernel(
    const float* __restrict__ bfc2, float* __restrict__ out)
{
    extern __shared__ char smc[];
    bf16*  Ab0  = (bf16*)smc;
    bf16*  Ab1  = (bf16*)(smc + 26624);
    bf16*  Bb0  = (bf16*)(smc + 2 * 26624);
    bf16*  Bb1  = (bf16*)(smc + 2 * 26624 + 19968);
    float* epi  = (float*)(smc + 2 * 26624 + 2 * 19968);

    const int tid = threadIdx.x, wid = tid >> 5, lane = tid & 31;
    const int row0 = blockIdx.x * 128;
    const int n0 = blockIdx.y * 96;
    const int mt = wid & 3, ng = wid >> 2;
    float* ws = epi + wid * 320;

    copy_A_chunk(Ab0, g_hmid + (size_t)row0 * 768, 768, tid);
    copy_B_tile(Bb0, g_wfc2, 768, n0, 0, tid);
    CP_COMMIT();

    FC acc[6];
#pragma unroll
    for (int j = 0; j < 6; j++) wmma::fill_fragment(acc[j], 0.f);

    for (int t = 0; t < 8; t++) {
        bf16* Acur = (t & 1) ? Ab1 : Ab0;
        bf16* Bcur = (t & 1) ? Bb1 : Bb0;
        bf16* Anxt = (t & 1) ? Ab0 : Ab1;
        bf16* Bnxt = (t & 1) ? Bb0 : Bb1;
        CP_WAIT0();
        __syncthreads();
        if (t + 1 < 8) {
            copy_A_chunk(Anxt, g_hmid + (size_t)row0 * 768 + (t + 1) * 96, 768, tid);
            copy_B_tile(Bnxt, g_wfc2, 768, n0, (t + 1) * 96, tid);
            CP_COMMIT();
        }
        mma_chunk(Acur, 104, 0, Bcur, mt, ng, acc);
    }
    epi_frags<3>(ws, acc, mt, ng, n0, row0, (const float*)0, bfc2, out, lane);
}

// ---------------------------------------------------------------------------
// attention core per (window, head): S -> masked softmax -> PV
// ---------------------------------------------------------------------------
#define AT_SM 41984

__global__ __launch_bounds__(256) void attn_core(const int* __restrict__ mask)
{
    extern __shared__ char smc[];
    bf16*  qs    = (bf16*)smc;               // 64x40
    bf16*  ks    = (bf16*)(smc + 5120);
    bf16*  vs    = (bf16*)(smc + 10240);
    float* S     = (float*)(smc + 15360);    // 64x68 f32
    bf16*  P     = (bf16*)(smc + 32768);     // 64x72
    float* pvbuf = (float*)(smc + 15360);    // alias S

    const int tid = threadIdx.x, wid = tid >> 5, lane = tid & 31;
    const int win = blockIdx.x, h = blockIdx.y;
    const size_t base = (size_t)(win * 49) * 576;

    {
        const int r = tid >> 2, c8 = (tid & 3) * 8;
        uint4 z; z.x = z.y = z.z = z.w = 0u;
#pragma unroll
        for (int m = 0; m < 3; m++) {
            bf16* dst = (m == 0) ? qs : ((m == 1) ? ks : vs);
            uint4 val = z;
            if (r < 49)
                val = *(const uint4*)(g_qkv + base + (size_t)r * 576 + m * 192 + h * 32 + c8);
            *(uint4*)(dst + r * 40 + c8) = val;
        }
    }
    __syncthreads();

#pragma unroll
    for (int it = 0; it < 2; it++) {
        int t = wid + it * 8;
        int mt = t & 3, nt = t >> 2;
        FC c;
        wmma::fill_fragment(c, 0.f);
#pragma unroll
        for (int k0 = 0; k0 < 32; k0 += 16) {
            FA a;
            wmma::load_matrix_sync(a, qs + mt * 16 * 40 + k0, 40);
            FBc b;
            wmma::load_matrix_sync(b, ks + nt * 16 * 40 + k0, 40);
            wmma::mma_sync(c, a, b, c);
        }
        wmma::store_matrix_sync(S + mt * 16 * 68 + nt * 16, c, 68, wmma::mem_row_major);
    }
    __syncthreads();

    {
        const float scale = 0.17677669529663687f;
        const int* mrow_base = mask + (size_t)win * 49 * 49;
        for (int r = wid; r < 49; r += 8) {
            const int* mrow = mrow_base + r * 49;
            int j2 = lane + 32;
            float s1 = (mrow[lane] == 0) ? -1e30f : S[r * 68 + lane] * scale;
            float s2 = (j2 < 49 && mrow[j2] != 0) ? S[r * 68 + j2] * scale : -1e30f;
            float m = fmaxf(s1, s2);
#pragma unroll
            for (int o = 16; o; o >>= 1) m = fmaxf(m, __shfl_xor_sync(0xffffffffu, m, o));
            float e1 = __expf(s1 - m);
            float e2 = (j2 < 49) ? __expf(s2 - m) : 0.f;
            float sum = e1 + e2;
#pragma unroll
            for (int o = 16; o; o >>= 1) sum += __shfl_xor_sync(0xffffffffu, sum, o);
            float inv = 1.f / sum;
            P[r * 72 + lane] = __float2bfloat16(e1 * inv);
            P[r * 72 + j2]   = __float2bfloat16(e2 * inv);
        }
    }
    __syncthreads();

    {
        int mt = wid & 3, nt = wid >> 2;
        FC c;
        wmma::fill_fragment(c, 0.f);
#pragma unroll
        for (int k0 = 0; k0 < 64; k0 += 16) {
            FA a;
            wmma::load_matrix_sync(a, P + mt * 16 * 72 + k0, 72);
            FBr b;
            wmma::load_matrix_sync(b, vs + k0 * 40 + nt * 16, 40);
            wmma::mma_sync(c, a, b, c);
        }
        wmma::store_matrix_sync(pvbuf + mt * 16 * 40 + nt * 16, c, 40, wmma::mem_row_major);
    }
    __syncthreads();

    for (int idx = tid; idx < 49 * 32; idx += 256) {
        int r = idx >> 5, c = idx & 31;
        g_attno[(size_t)(win * 49 + r) * 192 + h * 32 + c] = __float2bfloat16(pvbuf[r * 40 + c]);
    }
}

// ---------------------------------------------------------------------------

extern "C" void kernel_launch(void* const* d_in, const int* in_sizes, int n_in,
                              void* d_out, int out_size)
{
    const float* x     = (const float*)d_in[0];
    const int*   msk   = (const int*)  d_in[1];
    const float* ln1g  = (const float*)d_in[2];
    const float* ln1b  = (const float*)d_in[3];
    const float* bqkv  = (const float*)d_in[5];
    const float* bproj = (const float*)d_in[7];
    const float* ln2g  = (const float*)d_in[8];
    const float* ln2b  = (const float*)d_in[9];
    const float* bfc1  = (const float*)d_in[11];
    const float* bfc2  = (const float*)d_in[13];
    float* out = (float*)d_out;

    cudaFuncSetAttribute(gemm192_kernel<6, 0>, cudaFuncAttributeMaxDynamicSharedMemorySize, G192_SM);
    cudaFuncSetAttribute(gemm192_kernel<2, 1>, cudaFuncAttributeMaxDynamicSharedMemorySize, G192_SM);
    cudaFuncSetAttribute(gemm192_kernel<8, 2>, cudaFuncAttributeMaxDynamicSharedMemorySize, G192_SM);
    cudaFuncSetAttribute(fc2_kernel, cudaFuncAttributeMaxDynamicSharedMemorySize, FC2_SM);
    cudaFuncSetAttribute(attn_core,  cudaFuncAttributeMaxDynamicSharedMemorySize, AT_SM);

    cvt_all<<<576, 256>>>((const float*)d_in[4], (const float*)d_in[6],
                          (const float*)d_in[10], (const float*)d_in[12]);
    gemm192_kernel<6, 0><<<1568, 256, G192_SM>>>(x, ln1g, ln1b, bqkv);
    attn_core<<<dim3(4096, 6), 256, AT_SM>>>(msk);
    gemm192_kernel<2, 1><<<1568, 256, G192_SM>>>(x, (const float*)0, (const float*)0, bproj);
    gemm192_kernel<8, 2><<<1568, 256, G192_SM>>>((const float*)0, ln2g, ln2b, bfc1);
    fc2_kernel<<<dim3(1568, 2), 256, FC2_SM>>>(bfc2, out);
}